// round 2
// baseline (speedup 1.0000x reference)
#include <cuda_runtime.h>

// Batched 12-qubit state-vector simulator.
// One CTA per batch element; state (4096 complex) lives in SMEM as AoS float2.
// RX*RY*RZ (+ RY embedding in layer 0) fused into one generic 2x2 per qubit.

#define NQ     12
#define DIM    (1 << NQ)          // 4096
#define NPARAM (NQ * 4 * 5)       // 240
#define NT     256
#define NW     (NT / 32)

struct C2 { float r, i; };
__device__ __forceinline__ C2 cmul(C2 a, C2 b) { return { a.r*b.r - a.i*b.i, a.r*b.i + a.i*b.r }; }
__device__ __forceinline__ C2 cadd(C2 a, C2 b) { return { a.r + b.r, a.i + b.i }; }

struct M2 { C2 a, b, c, d; };
__device__ __forceinline__ M2 mmul(const M2& x, const M2& y) {
    M2 r;
    r.a = cadd(cmul(x.a, y.a), cmul(x.b, y.c));
    r.b = cadd(cmul(x.a, y.b), cmul(x.b, y.d));
    r.c = cadd(cmul(x.c, y.a), cmul(x.d, y.c));
    r.d = cadd(cmul(x.c, y.b), cmul(x.d, y.d));
    return r;
}

__global__ void __launch_bounds__(NT, 1)
qsim_kernel(const float* __restrict__ params,
            const float* __restrict__ inputs,
            float* __restrict__ out)
{
    __shared__ float2 st[DIM];               // state, AoS (re, im)
    __shared__ float  pc[NPARAM + NQ];
    __shared__ float  ps[NPARAM + NQ];
    __shared__ float  wred[3][NW];

    const int tid = threadIdx.x;
    const int b   = blockIdx.x;

    // Precompute half-angle trig for all params + embedding inputs (once per CTA).
    for (int t = tid; t < NPARAM + NQ; t += NT) {
        float th = (t < NPARAM) ? params[(size_t)b * NPARAM + t]
                                : inputs[(size_t)b * NQ + (t - NPARAM)];
        float s, c;
        sincosf(0.5f * th, &s, &c);
        pc[t] = c; ps[t] = s;
    }
    // |0...0>
    for (int i = tid; i < DIM; i += NT) st[i] = make_float2(0.f, 0.f);
    __syncthreads();
    if (tid == 0) st[0] = make_float2(1.f, 0.f);
    __syncthreads();

    // Generic 1q gate on `bit` (qubit q has bit = 11 - q in the flat index).
    auto apply1q = [&](int bit, const M2& m) {
        const int mask = (1 << bit) - 1;
        const int hbit = 1 << bit;
#pragma unroll
        for (int k = 0; k < DIM / 2 / NT; k++) {
            int j  = tid + k * NT;
            int i0 = ((j & ~mask) << 1) | (j & mask);
            int i1 = i0 | hbit;
            float2 v0 = st[i0];
            float2 v1 = st[i1];
            C2 s0 = { v0.x, v0.y };
            C2 s1 = { v1.x, v1.y };
            C2 n0 = cadd(cmul(m.a, s0), cmul(m.b, s1));
            C2 n1 = cadd(cmul(m.c, s0), cmul(m.d, s1));
            st[i0] = make_float2(n0.r, n0.i);
            st[i1] = make_float2(n1.r, n1.i);
        }
        __syncthreads();
    };

    // CRX(control bit cbit, target bit tbit): RX on target where control = 1.
    auto crx = [&](int cbit, int tbit, float c, float s) {
        const int lo = (cbit < tbit) ? cbit : tbit;
        const int hi = (cbit < tbit) ? tbit : cbit;
        const int lmask = (1 << lo) - 1;
        const int hmask = (1 << hi) - 1;
#pragma unroll
        for (int k = 0; k < DIM / 4 / NT; k++) {
            int j  = tid + k * NT;
            int t0 = ((j  >> lo) << (lo + 1)) | (j  & lmask);
            int t1 = ((t0 >> hi) << (hi + 1)) | (t0 & hmask);
            int i0 = t1 | (1 << cbit);
            int i1 = i0 | (1 << tbit);
            float2 v0 = st[i0];
            float2 v1 = st[i1];
            // n0 = c*s0 - i*s*s1 ; n1 = c*s1 - i*s*s0
            st[i0] = make_float2(c * v0.x + s * v1.y, c * v0.y - s * v1.x);
            st[i1] = make_float2(c * v1.x + s * v0.y, c * v1.y - s * v0.x);
        }
        __syncthreads();
    };

    int p = 0;
#pragma unroll 1
    for (int layer = 0; layer < 4; layer++) {
        // Rotation block: fused RZ * RY * RX (* RY_embed on layer 0) per qubit.
#pragma unroll 1
        for (int q = 0; q < NQ; q++) {
            float cx = pc[p],     sx = ps[p];
            float cy = pc[p + 1], sy = ps[p + 1];
            float cz = pc[p + 2], sz = ps[p + 2];
            M2 rx = { {cx, 0.f}, {0.f, -sx}, {0.f, -sx}, {cx, 0.f} };
            M2 ry = { {cy, 0.f}, {-sy, 0.f}, {sy, 0.f},  {cy, 0.f} };
            M2 rz = { {cz, -sz}, {0.f, 0.f}, {0.f, 0.f}, {cz, sz} };
            M2 m  = mmul(rz, mmul(ry, rx));
            if (layer == 0) {
                float ce = pc[NPARAM + q], se = ps[NPARAM + q];
                M2 rye = { {ce, 0.f}, {-se, 0.f}, {se, 0.f}, {ce, 0.f} };
                m = mmul(m, rye);
            }
            p += 3;
            apply1q(11 - q, m);
        }
        // Forward ring: CRX(i, (i+1)%n)
#pragma unroll 1
        for (int q = 0; q < NQ; q++) {
            crx(11 - q, 11 - ((q + 1) % NQ), pc[p], ps[p]);
            p++;
        }
        // Backward ring: CRX(i, (i-1)%n), i = n-1 .. 0
#pragma unroll 1
        for (int q = NQ - 1; q >= 0; q--) {
            crx(11 - q, 11 - ((q + NQ - 1) % NQ), pc[p], ps[p]);
            p++;
        }
    }

    // Expectation values: X_i = 2 Re<s0|s1>, Y_i = 2 Im<s0|s1>, Z_i = |s0|^2-|s1|^2.
#pragma unroll 1
    for (int q = 0; q < NQ; q++) {
        const int bit  = 11 - q;
        const int mask = (1 << bit) - 1;
        float xr = 0.f, xi = 0.f, zz = 0.f;
#pragma unroll
        for (int k = 0; k < DIM / 2 / NT; k++) {
            int j  = tid + k * NT;
            int i0 = ((j & ~mask) << 1) | (j & mask);
            int i1 = i0 | (1 << bit);
            float2 v0 = st[i0];
            float2 v1 = st[i1];
            xr += v0.x * v1.x + v0.y * v1.y;     // Re(conj(s0)*s1)
            xi += v0.x * v1.y - v0.y * v1.x;     // Im(conj(s0)*s1)
            zz += (v0.x * v0.x + v0.y * v0.y) - (v1.x * v1.x + v1.y * v1.y);
        }
#pragma unroll
        for (int o = 16; o; o >>= 1) {
            xr += __shfl_down_sync(0xffffffffu, xr, o);
            xi += __shfl_down_sync(0xffffffffu, xi, o);
            zz += __shfl_down_sync(0xffffffffu, zz, o);
        }
        if ((tid & 31) == 0) {
            int w = tid >> 5;
            wred[0][w] = xr; wred[1][w] = xi; wred[2][w] = zz;
        }
        __syncthreads();
        if (tid == 0) {
            float X = 0.f, Y = 0.f, Z = 0.f;
#pragma unroll
            for (int w = 0; w < NW; w++) { X += wred[0][w]; Y += wred[1][w]; Z += wred[2][w]; }
            out[(size_t)b * (3 * NQ) + q]          = 2.f * X;
            out[(size_t)b * (3 * NQ) + NQ + q]     = 2.f * Y;
            out[(size_t)b * (3 * NQ) + 2 * NQ + q] = Z;
        }
        __syncthreads();
    }
}

extern "C" void kernel_launch(void* const* d_in, const int* in_sizes, int n_in,
                              void* d_out, int out_size)
{
    const float* params = (const float*)d_in[0];
    const float* inputs = (const float*)d_in[1];
    int sz_p = in_sizes[0], sz_i = in_sizes[1];
    if (n_in >= 2 && sz_p < sz_i) {  // robust to input ordering
        const float* t = params; params = inputs; inputs = t;
        int ts = sz_p; sz_p = sz_i; sz_i = ts;
    }
    int B = sz_p / NPARAM;  // 1024
    qsim_kernel<<<B, NT>>>(params, inputs, (float*)d_out);
}

// round 8
// speedup vs baseline: 2.6929x; 2.6929x over previous
#include <cuda_runtime.h>

// Batched 12-qubit state-vector simulator, sweep-fused.
// One CTA per batch element; state in SMEM (XOR-swizzled float2).
// Each sweep: thread loads a 4-bit-aligned hexadec (16 amps) into registers,
// applies fused rotation gates + 3 chain-CRX edges, stores back.

#define NQ     12
#define DIM    (1 << NQ)          // 4096
#define NPARAM (NQ * 4 * 5)       // 240
#define NT     256
#define NW     (NT / 32)

// ---------------- complex helpers (for matrix precompute) ----------------
struct C2 { float r, i; };
__device__ __forceinline__ C2 cmul(C2 a, C2 b) { return { a.r*b.r - a.i*b.i, a.r*b.i + a.i*b.r }; }
__device__ __forceinline__ C2 cadd(C2 a, C2 b) { return { a.r + b.r, a.i + b.i }; }
struct M2 { C2 a, b, c, d; };
__device__ __forceinline__ M2 mmul(const M2& x, const M2& y) {
    M2 r;
    r.a = cadd(cmul(x.a, y.a), cmul(x.b, y.c));
    r.b = cadd(cmul(x.a, y.b), cmul(x.b, y.d));
    r.c = cadd(cmul(x.c, y.a), cmul(x.d, y.c));
    r.d = cadd(cmul(x.c, y.b), cmul(x.d, y.d));
    return r;
}

struct M2F { float ar, ai, br, bi, cr, ci, dr, di; };

__device__ __forceinline__ M2F ldmat(const float* p) {
    float4 a = *reinterpret_cast<const float4*>(p);
    float4 b = *reinterpret_cast<const float4*>(p + 4);
    return { a.x, a.y, a.z, a.w, b.x, b.y, b.z, b.w };
}

// XOR swizzle: conflict-free (per half-warp) for every circular 4-bit group.
__device__ __forceinline__ int physof(int i) { return i ^ ((i >> 4) & 15) ^ ((i >> 8) & 15); }

// Deposit 8 bits of t into the 12-bit positions NOT in MASK.
template<int MASK>
__device__ __forceinline__ int pdep8(int t) {
    int base = 0;
#pragma unroll
    for (int p = 0; p < 12; p++) {
        if (!((MASK >> p) & 1)) { base |= (t & 1) << p; t >>= 1; }
    }
    return base;
}

// Generic complex 2x2 gate on local bit LB of the 16-amp register block.
template<int LB>
__device__ __forceinline__ void rot16(float2 v[16], M2F g) {
#pragma unroll
    for (int m = 0; m < 16; m++) {
        if (!((m >> LB) & 1)) {
            int j = m | (1 << LB);
            float x0 = v[m].x, y0 = v[m].y, x1 = v[j].x, y1 = v[j].y;
            v[m].x = g.ar*x0 - g.ai*y0 + g.br*x1 - g.bi*y1;
            v[m].y = g.ar*y0 + g.ai*x0 + g.br*y1 + g.bi*x1;
            v[j].x = g.cr*x0 - g.ci*y0 + g.dr*x1 - g.di*y1;
            v[j].y = g.cr*y0 + g.ci*x0 + g.dr*y1 + g.di*x1;
        }
    }
}

// CRX: control local bit CB, target local bit TB. c=cos(th/2), s=sin(th/2).
template<int CB, int TB>
__device__ __forceinline__ void crx16(float2 v[16], float c, float s) {
#pragma unroll
    for (int m = 0; m < 16; m++) {
        if (((m >> CB) & 1) && !((m >> TB) & 1)) {
            int j = m | (1 << TB);
            float x0 = v[m].x, y0 = v[m].y, x1 = v[j].x, y1 = v[j].y;
            v[m].x = c*x0 + s*y1;  v[m].y = c*y0 - s*x1;
            v[j].x = c*x1 + s*y0;  v[j].y = c*y1 - s*x0;
        }
    }
}

// One sweep: local chain bits at positions B0..B3 (chain order), optional
// rotations (RM bitmask over chain positions, matrix row indices g0..g3 into
// sm), then CRX edges (0->1),(1->2),(2->3).
template<int B0, int B1, int B2, int B3, int RM>
__device__ __forceinline__ void sweep(float2* st, int tid, const float* sm,
                                      int g0, int g1, int g2, int g3,
                                      float c0, float s0, float c1, float s1,
                                      float c2, float s2)
{
    constexpr int MASK = (1 << B0) | (1 << B1) | (1 << B2) | (1 << B3);
    const int pbase = physof(pdep8<MASK>(tid));
    float2 v[16];
#pragma unroll
    for (int m = 0; m < 16; m++) {
        int place = ((m & 1) << B0) | (((m >> 1) & 1) << B1)
                  | (((m >> 2) & 1) << B2) | (((m >> 3) & 1) << B3);
        v[m] = st[pbase ^ physof(place)];
    }
    if (RM & 1) rot16<0>(v, ldmat(sm + g0 * 8));
    if (RM & 2) rot16<1>(v, ldmat(sm + g1 * 8));
    if (RM & 4) rot16<2>(v, ldmat(sm + g2 * 8));
    if (RM & 8) rot16<3>(v, ldmat(sm + g3 * 8));
    crx16<0, 1>(v, c0, s0);
    crx16<1, 2>(v, c1, s1);
    crx16<2, 3>(v, c2, s2);
#pragma unroll
    for (int m = 0; m < 16; m++) {
        int place = ((m & 1) << B0) | (((m >> 1) & 1) << B1)
                  | (((m >> 2) & 1) << B2) | (((m >> 3) & 1) << B3);
        st[pbase ^ physof(place)] = v[m];
    }
}

// Expectation contributions for the 4 local bits of one group.
template<int B0, int B1, int B2, int B3>
__device__ __forceinline__ void expect4(const float2* st, int tid, float* sred)
{
    constexpr int MASK = (1 << B0) | (1 << B1) | (1 << B2) | (1 << B3);
    const int pbase = physof(pdep8<MASK>(tid));
    float2 v[16];
#pragma unroll
    for (int m = 0; m < 16; m++) {
        int place = ((m & 1) << B0) | (((m >> 1) & 1) << B1)
                  | (((m >> 2) & 1) << B2) | (((m >> 3) & 1) << B3);
        v[m] = st[pbase ^ physof(place)];
    }
    const int bits[4] = { B0, B1, B2, B3 };
#pragma unroll
    for (int k = 0; k < 4; k++) {
        float xr = 0.f, xi = 0.f, zz = 0.f;
#pragma unroll
        for (int m = 0; m < 16; m++) {
            if (!((m >> k) & 1)) {
                float2 a = v[m], c = v[m | (1 << k)];
                xr += a.x * c.x + a.y * c.y;
                xi += a.x * c.y - a.y * c.x;
                zz += a.x * a.x + a.y * a.y - c.x * c.x - c.y * c.y;
            }
        }
#pragma unroll
        for (int o = 16; o; o >>= 1) {
            xr += __shfl_down_sync(0xffffffffu, xr, o);
            xi += __shfl_down_sync(0xffffffffu, xi, o);
            zz += __shfl_down_sync(0xffffffffu, zz, o);
        }
        if ((tid & 31) == 0) {
            int q = 11 - bits[k];            // qubit index (bit b <-> qubit 11-b)
            int w = tid >> 5;
            sred[(q * 3 + 0) * NW + w] = xr;
            sred[(q * 3 + 1) * NW + w] = xi;
            sred[(q * 3 + 2) * NW + w] = zz;
        }
    }
}

__global__ void __launch_bounds__(NT, 3)
qsim_kernel(const float* __restrict__ params,
            const float* __restrict__ inputs,
            float* __restrict__ out)
{
    __shared__ float2 st[DIM];
    __shared__ float pc[NPARAM + NQ], ps[NPARAM + NQ];
    __shared__ alignas(16) float smats[48 * 8];
    __shared__ float sred[36 * NW];

    const int tid = threadIdx.x;
    const int b   = blockIdx.x;

    // half-angle trig for all params + embedding inputs
    for (int t = tid; t < NPARAM + NQ; t += NT) {
        float th = (t < NPARAM) ? params[(size_t)b * NPARAM + t]
                                : inputs[(size_t)b * NQ + (t - NPARAM)];
        float s, c;
        sincosf(0.5f * th, &s, &c);
        pc[t] = c; ps[t] = s;
    }
    for (int i = tid; i < DIM; i += NT) st[i] = make_float2(0.f, 0.f);
    __syncthreads();

    // Precompute fused rotation matrices: one thread per (layer, qubit).
    if (tid < 48) {
        int l = tid / 12, q = tid % 12;
        int p = l * 60 + q * 3;
        float cx = pc[p],     sx = ps[p];
        float cy = pc[p + 1], sy = ps[p + 1];
        float cz = pc[p + 2], sz = ps[p + 2];
        M2 rx = { {cx, 0.f}, {0.f, -sx}, {0.f, -sx}, {cx, 0.f} };
        M2 ry = { {cy, 0.f}, {-sy, 0.f}, {sy, 0.f},  {cy, 0.f} };
        M2 rz = { {cz, -sz}, {0.f, 0.f}, {0.f, 0.f}, {cz, sz} };
        M2 mm = mmul(rz, mmul(ry, rx));
        if (l == 0) {
            float ce = pc[NPARAM + q], se = ps[NPARAM + q];
            M2 rye = { {ce, 0.f}, {-se, 0.f}, {se, 0.f}, {ce, 0.f} };
            mm = mmul(mm, rye);
        }
        float* o = smats + tid * 8;
        o[0] = mm.a.r; o[1] = mm.a.i; o[2] = mm.b.r; o[3] = mm.b.i;
        o[4] = mm.c.r; o[5] = mm.c.i; o[6] = mm.d.r; o[7] = mm.d.i;
    }
    if (tid == 0) st[0] = make_float2(1.f, 0.f);   // physof(0) == 0
    __syncthreads();

    // Qubit q lives on bit 11-q. Forward ring CRX(q,q+1); backward CRX(q,q-1).
#pragma unroll 1
    for (int l = 0; l < 4; l++) {
        const float* SM = smats + l * 96;
        const int pf = l * 60 + 36;    // forward-ring params, control qubit q -> pf+q
        const int pb = l * 60 + 48;    // backward-ring params, control qubit q -> pb+(11-q)

        // qubits 0,1,2,3 (bits 11,10,9,8): rot0..3 + CRX(0,1),(1,2),(2,3)
        sweep<11,10,9,8, 0xF>(st, tid, SM, 0,1,2,3,
            pc[pf+0],ps[pf+0], pc[pf+1],ps[pf+1], pc[pf+2],ps[pf+2]);
        __syncthreads();
        // qubits 3,4,5,6 (bits 8,7,6,5): rot4,5,6 + CRX(3,4),(4,5),(5,6)
        sweep<8,7,6,5, 0xE>(st, tid, SM, 0,4,5,6,
            pc[pf+3],ps[pf+3], pc[pf+4],ps[pf+4], pc[pf+5],ps[pf+5]);
        __syncthreads();
        // qubits 6,7,8,9 (bits 5,4,3,2): rot7,8,9 + CRX(6,7),(7,8),(8,9)
        sweep<5,4,3,2, 0xE>(st, tid, SM, 0,7,8,9,
            pc[pf+6],ps[pf+6], pc[pf+7],ps[pf+7], pc[pf+8],ps[pf+8]);
        __syncthreads();
        // qubits 9,10,11,0 (bits 2,1,0,11): rot10,11 + CRX(9,10),(10,11),(11,0)
        sweep<2,1,0,11, 0x6>(st, tid, SM, 0,10,11,0,
            pc[pf+9],ps[pf+9], pc[pf+10],ps[pf+10], pc[pf+11],ps[pf+11]);
        __syncthreads();
        // backward: qubits 11,10,9,8 (bits 0,1,2,3): CRX(11,10),(10,9),(9,8)
        sweep<0,1,2,3, 0>(st, tid, SM, 0,0,0,0,
            pc[pb+0],ps[pb+0], pc[pb+1],ps[pb+1], pc[pb+2],ps[pb+2]);
        __syncthreads();
        // qubits 8,7,6,5 (bits 3,4,5,6): CRX(8,7),(7,6),(6,5)
        sweep<3,4,5,6, 0>(st, tid, SM, 0,0,0,0,
            pc[pb+3],ps[pb+3], pc[pb+4],ps[pb+4], pc[pb+5],ps[pb+5]);
        __syncthreads();
        // qubits 5,4,3,2 (bits 6,7,8,9): CRX(5,4),(4,3),(3,2)
        sweep<6,7,8,9, 0>(st, tid, SM, 0,0,0,0,
            pc[pb+6],ps[pb+6], pc[pb+7],ps[pb+7], pc[pb+8],ps[pb+8]);
        __syncthreads();
        // qubits 2,1,0,11 (bits 9,10,11,0): CRX(2,1),(1,0),(0,11)
        sweep<9,10,11,0, 0>(st, tid, SM, 0,0,0,0,
            pc[pb+9],ps[pb+9], pc[pb+10],ps[pb+10], pc[pb+11],ps[pb+11]);
        __syncthreads();
    }

    // Expectation values, 3 register passes covering all 12 bits.
    expect4<0, 1, 2, 3>(st, tid, sred);
    expect4<4, 5, 6, 7>(st, tid, sred);
    expect4<8, 9, 10, 11>(st, tid, sred);
    __syncthreads();

    if (tid < 36) {
        float a = 0.f;
#pragma unroll
        for (int w = 0; w < NW; w++) a += sred[tid * NW + w];
        int q = tid / 3, comp = tid - q * 3;
        float val = (comp == 2) ? a : 2.f * a;
        out[(size_t)b * 36 + comp * 12 + q] = val;
    }
}

extern "C" void kernel_launch(void* const* d_in, const int* in_sizes, int n_in,
                              void* d_out, int out_size)
{
    const float* params = (const float*)d_in[0];
    const float* inputs = (const float*)d_in[1];
    int sz_p = in_sizes[0], sz_i = in_sizes[1];
    if (n_in >= 2 && sz_p < sz_i) {  // robust to input ordering
        const float* t = params; params = inputs; inputs = t;
        int ts = sz_p; sz_p = sz_i; sz_i = ts;
    }
    int B = sz_p / NPARAM;  // 1024
    qsim_kernel<<<B, NT>>>(params, inputs, (float*)d_out);
}